// round 10
// baseline (speedup 1.0000x reference)
#include <cuda_runtime.h>

#define B_ 256
#define T_ 1024
#define K_ 128

__device__ float g_denom[B_];
__device__ float g_num[B_];

typedef unsigned long long u64;

__device__ __forceinline__ void ffma2(u64 &d, u64 a, u64 b) {
    asm("fma.rn.f32x2 %0, %1, %2, %0;" : "+l"(d) : "l"(a), "l"(b));
}
__device__ __forceinline__ u64 fadd2(u64 a, u64 b) {
    u64 r; asm("add.rn.f32x2 %0, %1, %2;" : "=l"(r) : "l"(a), "l"(b)); return r;
}
__device__ __forceinline__ u64 pack2(float lo, float hi) {
    u64 r; asm("mov.b64 %0, {%1, %2};" : "=l"(r) : "f"(lo), "f"(hi)); return r;
}
__device__ __forceinline__ void unpack2(u64 v, float &lo, float &hi) {
    asm("mov.b64 {%0, %1}, %2;" : "=f"(lo), "=f"(hi) : "l"(v));
}

// ---------------------------------------------------------------------------
// Forward algorithm, exponential domain:
//   p'_j = (sum_i p_i E_ij) * exp(emit_j) * (1/p_0);  C += log(p_0)
// 256 thr/block (vs 128 in R9): i-range split in half WITHIN each warp —
// lanes 0-15 handle i in [0,64), lanes 16-31 i in [64,128) for the same 16
// states; halves combine with one shfl_xor(16). Doubles warps/SMSP (latency
// hiding) while halving the per-warp dependency chain. 4-deep emission
// register ring keeps the DRAM stream off the recurrence path (R9's win).
// ---------------------------------------------------------------------------
__global__ void __launch_bounds__(256, 2) forward_kernel(
    const float* inp, const float* trans, const int* mask) {
    const int b   = blockIdx.x;
    const int tid = threadIdx.x;
    const int w   = tid >> 5;               // warp 0..7
    const int l   = tid & 31;
    const int h   = l >> 4;                 // i-half: 0 or 1
    const int j   = w * 16 + (l & 15);      // output state 0..127

    __shared__ __align__(16) float pbuf[2][K_];
    __shared__ int smask[T_];

    for (int t = tid; t < T_; t += 256) smask[t] = mask[(size_t)b * T_ + t];

    // E2[m] = pack(E[i][j], E[i+1][j]), i = 64h + 2m — my half of column j.
    u64 E2[32];
#pragma unroll
    for (int m = 0; m < 32; m++) {
        const int i = (h << 6) + 2 * m;
        E2[m] = pack2(__expf(trans[i * K_ + j]),
                      __expf(trans[(i + 1) * K_ + j]));
    }

    const float* eb = inp + (size_t)b * T_ * K_;

    const float p_init = __expf(eb[j]);       // t = 0
    if (h == 0) pbuf[0][j] = p_init;
    float pcur = p_init;
    float C = 0.0f;

    // emission pipeline: ee = exp(emit[t]); r1..r4 = raw emit[t+1..t+4]
    float ee = __expf(eb[K_ + j]);
    float r1 = eb[2 * K_ + j];
    float r2 = eb[3 * K_ + j];
    float r3 = eb[4 * K_ + j];
    float r4 = eb[5 * K_ + j];
    __syncthreads();

    int cur = 0;
    for (int t = 1; t < T_; t++) {
        const float rnew = (t + 5 < T_) ? eb[(size_t)(t + 5) * K_ + j] : 0.0f;
        const float ee2  = __expf(r1);        // exp(emit[t+1]), r1 aged 4 steps

        const int   mc  = smask[t];
        const float p0  = pbuf[cur][0];       // broadcast
        const float rp0 = __frcp_rn(p0);      // MUFU, parallel w/ FMA tree
        const float lp0 = __logf(p0);         // off-path (feeds C only)

        // my 64 p's as 16 packed quads
        const ulonglong2* pv = (const ulonglong2*)(pbuf[cur] + (h << 6));
        u64 acc[8];
#pragma unroll
        for (int q = 0; q < 8; q++) acc[q] = 0ULL;
#pragma unroll
        for (int k = 0; k < 16; k++) {
            const ulonglong2 u = pv[k];       // p[64h+4k .. +3]
            ffma2(acc[(2 * k)     & 7], u.x, E2[2 * k]);
            ffma2(acc[(2 * k + 1) & 7], u.y, E2[2 * k + 1]);
        }
        const u64 r = fadd2(fadd2(fadd2(acc[0], acc[1]), fadd2(acc[2], acc[3])),
                            fadd2(fadd2(acc[4], acc[5]), fadd2(acc[6], acc[7])));
        float lo, hi; unpack2(r, lo, hi);
        const float part = lo + hi;           // sum over my i-half
        const float s = part + __shfl_xor_sync(0xffffffffu, part, 16);

        const float pn   = s * (ee * rp0);    // = s * exp(emit - log p0)
        const float pnew = mc ? pn : pcur;    // masked step carries p
        C += mc ? lp0 : 0.0f;

        cur ^= 1;
        if (h == 0) pbuf[cur][j] = pnew;      // one owner per state
        pcur = pnew;
        __syncthreads();                      // one barrier per step

        ee = ee2;                             // rotate pipeline
        r1 = r2; r2 = r3; r3 = r4; r4 = rnew;
    }

    if (tid == 0) {
        float sum = 0.0f;                     // fixed order: deterministic
        for (int i = 0; i < K_; i++) sum += pbuf[cur][i];
        g_denom[b] = C + __logf(sum);
    }
}

// ---------------------------------------------------------------------------
// Joint (numerator) score. One block per batch, 128 threads strided over t.
// ---------------------------------------------------------------------------
__global__ void numerator_kernel(const float* inp, const float* trans,
                                 const int* tags, const int* mask) {
    const int b   = blockIdx.x;
    const int tid = threadIdx.x;        // 128
    const int*   tb = tags + (size_t)b * T_;
    const int*   mb = mask + (size_t)b * T_;
    const float* eb = inp  + (size_t)b * T_ * K_;

    float s = 0.0f;
    int msum = 0;
    for (int t = tid; t < T_; t += 128) {
        msum += mb[t];
        if (t < T_ - 1) {
            const int tg  = tb[t]     & (K_ - 1);
            const int tg1 = tb[t + 1] & (K_ - 1);
            s += trans[tg * K_ + tg1] * (float)mb[t + 1]
               + eb[(size_t)t * K_ + tg] * (float)mb[t];
        }
    }

    __shared__ float sf[128];
    __shared__ int   si[128];
    sf[tid] = s; si[tid] = msum;
    __syncthreads();
    for (int off = 64; off > 0; off >>= 1) {
        if (tid < off) { sf[tid] += sf[tid + off]; si[tid] += si[tid + off]; }
        __syncthreads();
    }
    if (tid == 0) {
        int last_idx = si[0] - 1;
        if (last_idx < 0)   last_idx = 0;
        if (last_idx >= T_) last_idx = T_ - 1;
        const int lt = tb[last_idx] & (K_ - 1);
        g_num[b] = sf[0]
                 + eb[(size_t)(T_ - 1) * K_ + lt] * (float)mb[T_ - 1];
    }
}

// ---------------------------------------------------------------------------
__global__ void final_kernel(float* out) {
    __shared__ float sd[B_];
    const int t = threadIdx.x;
    sd[t] = g_num[t] - g_denom[t];
    __syncthreads();
    for (int off = 128; off > 0; off >>= 1) {
        if (t < off) sd[t] += sd[t + off];
        __syncthreads();
    }
    if (t == 0) out[0] = sd[0];
}

// ---------------------------------------------------------------------------
extern "C" void kernel_launch(void* const* d_in, const int* in_sizes, int n_in,
                              void* d_out, int out_size) {
    const float* inp   = (const float*)d_in[0];   // (B,T,K) f32
    const float* trans = (const float*)d_in[1];   // (K,K)   f32
    const int*   tags  = (const int*)d_in[2];     // (B,T)   i32
    const int*   mask  = (const int*)d_in[3];     // (B,T)   i32
    float* out = (float*)d_out;

    forward_kernel<<<B_, 256>>>(inp, trans, mask);
    numerator_kernel<<<B_, 128>>>(inp, trans, tags, mask);
    final_kernel<<<1, B_>>>(out);
}

// round 11
// speedup vs baseline: 1.1269x; 1.1269x over previous
#include <cuda_runtime.h>

#define B_ 256
#define T_ 1024
#define K_ 128

__device__ float g_denom[B_];
__device__ float g_num[B_];

typedef unsigned long long u64;

__device__ __forceinline__ void ffma2(u64 &d, u64 a, u64 b) {
    asm("fma.rn.f32x2 %0, %1, %2, %0;" : "+l"(d) : "l"(a), "l"(b));
}
__device__ __forceinline__ u64 fadd2(u64 a, u64 b) {
    u64 r; asm("add.rn.f32x2 %0, %1, %2;" : "=l"(r) : "l"(a), "l"(b)); return r;
}
__device__ __forceinline__ u64 pack2(float lo, float hi) {
    u64 r; asm("mov.b64 %0, {%1, %2};" : "=l"(r) : "f"(lo), "f"(hi)); return r;
}
__device__ __forceinline__ void unpack2(u64 v, float &lo, float &hi) {
    asm("mov.b64 {%0, %1}, %2;" : "=f"(lo), "=f"(hi) : "l"(v));
}

// ---------------------------------------------------------------------------
// Forward algorithm, exponential domain:
//   p'_j = (sum_i p_i E_ij) * exp(emit_j) * (1/p_0);  C += log(p_0)
// TWO independent batches per block (128 threads each), each group
// synchronized by its OWN named barrier (bar.sync 1 / bar.sync 2). The two
// recurrences on an SMSP are phase-decoupled: when one group's warp waits at
// its barrier, the other issues — raising issue efficiency at ZERO extra
// instruction cost (unlike the R10 intra-warp split, which duplicated
// overhead). Per thread: full i-range, 32 broadcast LDS.128 + 64 f32x2 FMA.
// 4-deep emission register ring (R9's DRAM-latency win) kept.
// ---------------------------------------------------------------------------
__global__ void __launch_bounds__(256, 1) forward_kernel(
    const float* inp, const float* trans, const int* mask) {
    const int tid = threadIdx.x;
    const int g   = tid >> 7;                 // group 0/1 within block
    const int j   = tid & 127;                // output state
    const int b   = blockIdx.x * 2 + g;       // batch

    __shared__ __align__(16) float pbuf[2][2][K_];   // [group][buffer][state]
    __shared__ int smask[2][T_];
    const int bar_id = g + 1;                 // named barrier per group

    for (int t = j; t < T_; t += 128) smask[g][t] = mask[(size_t)b * T_ + t];

    // E2[m] = pack(E[2m][j], E[2m+1][j]) — column j as 64 packed pairs.
    u64 E2[64];
#pragma unroll
    for (int m = 0; m < 64; m++)
        E2[m] = pack2(__expf(trans[(2 * m) * K_ + j]),
                      __expf(trans[(2 * m + 1) * K_ + j]));

    const float* eb = inp + (size_t)b * T_ * K_;

    const float p_init = __expf(eb[j]);       // t = 0
    pbuf[g][0][j] = p_init;
    float pcur = p_init;
    float C = 0.0f;

    // emission pipeline: ee = exp(emit[t]); r1..r4 = raw emit[t+1..t+4]
    float ee = __expf(eb[K_ + j]);
    float r1 = eb[2 * K_ + j];
    float r2 = eb[3 * K_ + j];
    float r3 = eb[4 * K_ + j];
    float r4 = eb[5 * K_ + j];
    __syncthreads();                          // one full-block sync; loop uses
                                              // per-group named barriers only
    int cur = 0;
#pragma unroll 4
    for (int t = 1; t < T_; t++) {
        const float rnew = (t + 5 < T_) ? eb[(size_t)(t + 5) * K_ + j] : 0.0f;
        const float ee2  = __expf(r1);        // exp(emit[t+1]), aged 4 steps

        const int   mc  = smask[g][t];
        const float p0  = pbuf[g][cur][0];    // broadcast
        const float rp0 = __frcp_rn(p0);      // MUFU, parallel w/ FMA tree
        const float lp0 = __logf(p0);         // off-path (feeds C only)

        const ulonglong2* pv = (const ulonglong2*)pbuf[g][cur];
        u64 a0 = 0ULL, a1 = 0ULL, a2 = 0ULL, a3 = 0ULL;
#pragma unroll
        for (int k = 0; k < 32; k += 2) {     // full range: p[0..127]
            const ulonglong2 u = pv[k];
            ffma2(a0, u.x, E2[2 * k]);
            ffma2(a1, u.y, E2[2 * k + 1]);
            const ulonglong2 v = pv[k + 1];
            ffma2(a2, v.x, E2[2 * k + 2]);
            ffma2(a3, v.y, E2[2 * k + 3]);
        }
        const u64 r = fadd2(fadd2(a0, a1), fadd2(a2, a3));
        float lo, hi; unpack2(r, lo, hi);
        const float s = lo + hi;              // s_j = sum_i p_i E_ij

        const float pn   = s * (ee * rp0);    // = s * exp(emit - log p0)
        const float pnew = mc ? pn : pcur;    // masked step carries p
        C += mc ? lp0 : 0.0f;

        cur ^= 1;
        pbuf[g][cur][j] = pnew;
        pcur = pnew;
        asm volatile("bar.sync %0, 128;" :: "r"(bar_id) : "memory");

        ee = ee2;                             // ring rotates (renamed by unroll)
        r1 = r2; r2 = r3; r3 = r4; r4 = rnew;
    }

    if (j == 0) {                             // one writer per group
        float sum = 0.0f;                     // fixed order: deterministic
        for (int i = 0; i < K_; i++) sum += pbuf[g][cur][i];
        g_denom[b] = C + __logf(sum);
    }
}

// ---------------------------------------------------------------------------
// Joint (numerator) score. One block per batch, 128 threads strided over t.
// ---------------------------------------------------------------------------
__global__ void numerator_kernel(const float* inp, const float* trans,
                                 const int* tags, const int* mask) {
    const int b   = blockIdx.x;
    const int tid = threadIdx.x;        // 128
    const int*   tb = tags + (size_t)b * T_;
    const int*   mb = mask + (size_t)b * T_;
    const float* eb = inp  + (size_t)b * T_ * K_;

    float s = 0.0f;
    int msum = 0;
    for (int t = tid; t < T_; t += 128) {
        msum += mb[t];
        if (t < T_ - 1) {
            const int tg  = tb[t]     & (K_ - 1);
            const int tg1 = tb[t + 1] & (K_ - 1);
            s += trans[tg * K_ + tg1] * (float)mb[t + 1]
               + eb[(size_t)t * K_ + tg] * (float)mb[t];
        }
    }

    __shared__ float sf[128];
    __shared__ int   si[128];
    sf[tid] = s; si[tid] = msum;
    __syncthreads();
    for (int off = 64; off > 0; off >>= 1) {
        if (tid < off) { sf[tid] += sf[tid + off]; si[tid] += si[tid + off]; }
        __syncthreads();
    }
    if (tid == 0) {
        int last_idx = si[0] - 1;
        if (last_idx < 0)   last_idx = 0;
        if (last_idx >= T_) last_idx = T_ - 1;
        const int lt = tb[last_idx] & (K_ - 1);
        g_num[b] = sf[0]
                 + eb[(size_t)(T_ - 1) * K_ + lt] * (float)mb[T_ - 1];
    }
}

// ---------------------------------------------------------------------------
__global__ void final_kernel(float* out) {
    __shared__ float sd[B_];
    const int t = threadIdx.x;
    sd[t] = g_num[t] - g_denom[t];
    __syncthreads();
    for (int off = 128; off > 0; off >>= 1) {
        if (t < off) sd[t] += sd[t + off];
        __syncthreads();
    }
    if (t == 0) out[0] = sd[0];
}

// ---------------------------------------------------------------------------
extern "C" void kernel_launch(void* const* d_in, const int* in_sizes, int n_in,
                              void* d_out, int out_size) {
    const float* inp   = (const float*)d_in[0];   // (B,T,K) f32
    const float* trans = (const float*)d_in[1];   // (K,K)   f32
    const int*   tags  = (const int*)d_in[2];     // (B,T)   i32
    const int*   mask  = (const int*)d_in[3];     // (B,T)   i32
    float* out = (float*)d_out;

    forward_kernel<<<B_ / 2, 256>>>(inp, trans, mask);
    numerator_kernel<<<B_, 128>>>(inp, trans, tags, mask);
    final_kernel<<<1, B_>>>(out);
}

// round 12
// speedup vs baseline: 1.1999x; 1.0648x over previous
#include <cuda_runtime.h>

#define B_ 256
#define T_ 1024
#define K_ 128

__device__ float g_denom[B_];
__device__ float g_num[B_];

typedef unsigned long long u64;

__device__ __forceinline__ void ffma2(u64 &d, u64 a, u64 b) {
    asm("fma.rn.f32x2 %0, %1, %2, %0;" : "+l"(d) : "l"(a), "l"(b));
}
__device__ __forceinline__ u64 fadd2(u64 a, u64 b) {
    u64 r; asm("add.rn.f32x2 %0, %1, %2;" : "=l"(r) : "l"(a), "l"(b)); return r;
}
__device__ __forceinline__ u64 pack2(float lo, float hi) {
    u64 r; asm("mov.b64 %0, {%1, %2};" : "=l"(r) : "f"(lo), "f"(hi)); return r;
}
__device__ __forceinline__ void unpack2(u64 v, float &lo, float &hi) {
    asm("mov.b64 {%0, %1}, %2;" : "=f"(lo), "=f"(hi) : "l"(v));
}

// ---------------------------------------------------------------------------
// Forward + numerator fused in one launch:
//   blocks [0,128):   forward, 2 batches/block (2 groups of 128 threads)
//   blocks [128,384): numerator, 1 batch/block
//
// Forward group layout (128 thr): thread (w = t>>5, l = t&31) owns TWO states
//   jA = w*16 + (l&15), jB = jA + 64, and i-half h = l>>4 (64 i's).
// Each p-quad read feeds both states' FMAs -> LDS per thread 32 -> 16 at the
// same 64 FFMA2. p is stored PERMUTED (quad q -> slot 2*(q&15) + (q>>4)) so
// the two half-warps' LDS.128 addresses are 16B apart -> ONE wavefront per
// load (unpermuted they'd be 256B apart = 2 wavefronts). i-halves combine
// with one shfl_xor(16). Dual 4-deep emission rings keep DRAM off-path.
// ---------------------------------------------------------------------------
__global__ void __launch_bounds__(256, 1) fused_kernel(
    const float* inp, const float* trans, const int* tags, const int* mask) {
    const int tid = threadIdx.x;

    __shared__ __align__(16) float pbuf[2][2][K_];   // [group][buffer][slot]
    __shared__ int smask[2][T_];
    __shared__ float sf[256];
    __shared__ int   si[256];

    if (blockIdx.x < 128) {
        // ================= forward =================
        const int g    = tid >> 7;            // group 0/1
        const int t128 = tid & 127;
        const int w    = t128 >> 5;           // warp-in-group 0..3
        const int l    = t128 & 31;
        const int h    = l >> 4;              // i-half
        const int jlo  = w * 16 + (l & 15);   // 0..63
        const int jA = jlo, jB = jlo + 64;
        const int b  = blockIdx.x * 2 + g;
        // permuted store slot: j=4q+r -> slot 4*(2*(q&15)+(q>>4)) + r
        const int posA = ((jlo >> 2) << 3) | (jlo & 3);   // posB = posA + 4

        for (int t = t128; t < T_; t += 128)
            smask[g][t] = mask[(size_t)b * T_ + t];

        // E columns jA/jB for my i-half, as packed pairs matching quad order.
        u64 EA[32], EB[32];
#pragma unroll
        for (int m = 0; m < 32; m++) {
            const int i = (h << 6) + 2 * m;
            EA[m] = pack2(__expf(trans[i * K_ + jA]),
                          __expf(trans[(i + 1) * K_ + jA]));
            EB[m] = pack2(__expf(trans[i * K_ + jB]),
                          __expf(trans[(i + 1) * K_ + jB]));
        }

        const float* ebA = inp + (size_t)b * T_ * K_ + jA;
        const float* ebB = inp + (size_t)b * T_ * K_ + jB;

        float pcA = __expf(ebA[0]);           // t = 0
        float pcB = __expf(ebB[0]);
        if (h == 0) { pbuf[g][0][posA] = pcA; pbuf[g][0][posA + 4] = pcB; }
        float C = 0.0f;

        // dual emission rings: ee = exp(emit[t]); r1..r4 raw emit[t+1..t+4]
        float eeA = __expf(ebA[K_]),      eeB = __expf(ebB[K_]);
        float r1A = ebA[2 * K_], r1B = ebB[2 * K_];
        float r2A = ebA[3 * K_], r2B = ebB[3 * K_];
        float r3A = ebA[4 * K_], r3B = ebB[4 * K_];
        float r4A = ebA[5 * K_], r4B = ebB[5 * K_];
        __syncthreads();                      // covers smask + pbuf init
        int mnext = smask[g][1];

        const int bar_id = g + 1;
        int cur = 0;
#pragma unroll 2
        for (int t = 1; t < T_; t++) {
            const int i5 = (t + 5 < T_) ? (t + 5) : (T_ - 1);   // clamped
            const float rnA = ebA[(size_t)i5 << 7];
            const float rnB = ebB[(size_t)i5 << 7];
            const float eA2 = __expf(r1A);    // exp(emit[t+1]), aged 4 steps
            const float eB2 = __expf(r1B);
            const int   mc  = mnext;
            mnext = smask[g][(t + 1 < T_) ? (t + 1) : (T_ - 1)];

            const float p0  = pbuf[g][cur][0];     // slot 0 == state 0
            const float rp0 = __frcp_rn(p0);       // || with FMA tree
            const float lp0 = __logf(p0);          // off-path (C only)

            const ulonglong2* pvh =
                (const ulonglong2*)pbuf[g][cur] + h;   // +16B for half 1
            u64 aA0 = 0ULL, aA1 = 0ULL, aA2 = 0ULL, aA3 = 0ULL;
            u64 aB0 = 0ULL, aB1 = 0ULL, aB2 = 0ULL, aB3 = 0ULL;
#pragma unroll
            for (int k = 0; k < 16; k += 2) {
                const ulonglong2 u = pvh[2 * k];          // p[64h+4k..+3]
                ffma2(aA0, u.x, EA[2 * k]);     ffma2(aA1, u.y, EA[2 * k + 1]);
                ffma2(aB0, u.x, EB[2 * k]);     ffma2(aB1, u.y, EB[2 * k + 1]);
                const ulonglong2 v = pvh[2 * k + 2];      // next quad
                ffma2(aA2, v.x, EA[2 * k + 2]); ffma2(aA3, v.y, EA[2 * k + 3]);
                ffma2(aB2, v.x, EB[2 * k + 2]); ffma2(aB3, v.y, EB[2 * k + 3]);
            }
            const u64 rA = fadd2(fadd2(aA0, aA1), fadd2(aA2, aA3));
            const u64 rB = fadd2(fadd2(aB0, aB1), fadd2(aB2, aB3));
            float loA, hiA, loB, hiB;
            unpack2(rA, loA, hiA);
            unpack2(rB, loB, hiB);
            const float hA = loA + hiA, hB = loB + hiB;
            const float sA = hA + __shfl_xor_sync(0xffffffffu, hA, 16);
            const float sB = hB + __shfl_xor_sync(0xffffffffu, hB, 16);

            const float pnA = sA * (eeA * rp0);
            const float pnB = sB * (eeB * rp0);
            const float pwA = mc ? pnA : pcA;
            const float pwB = mc ? pnB : pcB;
            C += mc ? lp0 : 0.0f;

            cur ^= 1;
            if (h == 0) {
                pbuf[g][cur][posA]     = pwA;
                pbuf[g][cur][posA + 4] = pwB;
            }
            pcA = pwA; pcB = pwB;
            asm volatile("bar.sync %0, 128;" :: "r"(bar_id) : "memory");

            eeA = eA2; eeB = eB2;             // rotate rings
            r1A = r2A; r2A = r3A; r3A = r4A; r4A = rnA;
            r1B = r2B; r2B = r3B; r3B = r4B; r4B = rnB;
        }

        if (t128 == 0) {
            float sum = 0.0f;                 // fixed (permuted) order: determ.
            for (int i = 0; i < K_; i++) sum += pbuf[g][cur][i];
            g_denom[b] = C + __logf(sum);
        }
    } else {
        // ================= numerator =================
        const int b = blockIdx.x - 128;       // 0..255
        const int*   tb = tags + (size_t)b * T_;
        const int*   mb = mask + (size_t)b * T_;
        const float* eb = inp  + (size_t)b * T_ * K_;

        float s = 0.0f;
        int msum = 0;
        for (int t = tid; t < T_; t += 256) {
            msum += mb[t];
            if (t < T_ - 1) {
                const int tg  = tb[t]     & (K_ - 1);
                const int tg1 = tb[t + 1] & (K_ - 1);
                s += trans[tg * K_ + tg1] * (float)mb[t + 1]
                   + eb[(size_t)t * K_ + tg] * (float)mb[t];
            }
        }
        sf[tid] = s; si[tid] = msum;
        __syncthreads();
        for (int off = 128; off > 0; off >>= 1) {
            if (tid < off) { sf[tid] += sf[tid + off]; si[tid] += si[tid + off]; }
            __syncthreads();
        }
        if (tid == 0) {
            int last_idx = si[0] - 1;
            if (last_idx < 0)   last_idx = 0;
            if (last_idx >= T_) last_idx = T_ - 1;
            const int lt = tb[last_idx] & (K_ - 1);
            g_num[b] = sf[0]
                     + eb[(size_t)(T_ - 1) * K_ + lt] * (float)mb[T_ - 1];
        }
    }
}

// ---------------------------------------------------------------------------
__global__ void final_kernel(float* out) {
    __shared__ float sd[B_];
    const int t = threadIdx.x;
    sd[t] = g_num[t] - g_denom[t];
    __syncthreads();
    for (int off = 128; off > 0; off >>= 1) {
        if (t < off) sd[t] += sd[t + off];
        __syncthreads();
    }
    if (t == 0) out[0] = sd[0];
}

// ---------------------------------------------------------------------------
extern "C" void kernel_launch(void* const* d_in, const int* in_sizes, int n_in,
                              void* d_out, int out_size) {
    const float* inp   = (const float*)d_in[0];   // (B,T,K) f32
    const float* trans = (const float*)d_in[1];   // (K,K)   f32
    const int*   tags  = (const int*)d_in[2];     // (B,T)   i32
    const int*   mask  = (const int*)d_in[3];     // (B,T)   i32
    float* out = (float*)d_out;

    fused_kernel<<<128 + B_, 256>>>(inp, trans, tags, mask);
    final_kernel<<<1, B_>>>(out);
}